// round 10
// baseline (speedup 1.0000x reference)
#include <cuda_runtime.h>
#include <cstdint>
#include <math.h>

// Problem dims
#define B_DIM 128
#define S_DIM 1024
#define I_DIM 256
#define H_DIM 512
#define G4H   2048
#define O_DIM 10

// Recurrence partition: 128 persistent CTAs = 4 batch parts x 32 k parts
#define NCTA   128
#define PPARTS 4
#define QPARTS 32
#define BP (B_DIM/PPARTS)   // 32 batch rows per CTA
#define KP (H_DIM/QPARTS)   // 16 h-columns per CTA

#define WS_PITCH 516        // 512 + 4 pad -> conflict-free tf32 fragment LDS
#define GS_PITCH 68

// smem: W slice [64][516] u32 + h tile [32][516] u32 + gates [32][68] f32
#define SMEM_LSTM_BYTES ((64*WS_PITCH + 32*WS_PITCH)*4 + 32*GS_PITCH*4)

// Scratch (device globals: the sanctioned no-alloc workaround)
__device__ float g_xp[(size_t)S_DIM * B_DIM * G4H];   // 1 GB: x_proj in [s][b][g]
__device__ float g_h[2][B_DIM * H_DIM];               // ping-pong h
__device__ unsigned long long g_bar;                  // monotonic barrier counter

__device__ __forceinline__ uint32_t f2tf(float x) {
    uint32_t r;
    asm("cvt.rna.tf32.f32 %0, %1;" : "=r"(r) : "f"(x));
    return r;
}

__device__ __forceinline__ void mma8(float& d0, float& d1, float& d2, float& d3,
                                     uint32_t a0, uint32_t a1, uint32_t a2, uint32_t a3,
                                     uint32_t b0, uint32_t b1) {
    asm volatile(
        "mma.sync.aligned.m16n8k8.row.col.f32.tf32.tf32.f32 "
        "{%0,%1,%2,%3},{%4,%5,%6,%7},{%8,%9},{%0,%1,%2,%3};"
        : "+f"(d0), "+f"(d1), "+f"(d2), "+f"(d3)
        : "r"(a0), "r"(a1), "r"(a2), "r"(a3), "r"(b0), "r"(b1));
}

// ============================================================================
// Phase 1: x_proj[s][b][g] = sum_i x[b][s][i] * W_ih[g][i] + b_ih[g] + b_hh[g]
// CTA tile: M=128 (all batches of one s), N=128 gate cols, K=256 in 8 chunks.
// ============================================================================
__global__ __launch_bounds__(256) void xproj_kernel(
    const float* __restrict__ x, const float* __restrict__ Wih,
    const float* __restrict__ bih, const float* __restrict__ bhh) {
    __shared__ uint32_t As[128][36];
    __shared__ uint32_t Bs[128][36];

    const int s   = blockIdx.y;
    const int n0  = blockIdx.x * 128;
    const int tid = threadIdx.x;
    const int warp = tid >> 5, lane = tid & 31;
    const int gid = lane >> 2, tq = lane & 3;
    const int mw = warp >> 1, nw = warp & 1;   // 4 M-warps x 2 N-warps

    float acc[2][8][4] = {};

    for (int kc = 0; kc < I_DIM; kc += 32) {
        __syncthreads();
#pragma unroll
        for (int j = 0; j < 4; j++) {
            int id = tid + 256 * j;          // 1024 float4 per tile
            int r  = id >> 3;                // row 0..127
            int c  = (id & 7) * 4;           // col 0..28
            float4 av = *reinterpret_cast<const float4*>(
                x + ((size_t)r * S_DIM + s) * I_DIM + kc + c);
            As[r][c]   = f2tf(av.x); As[r][c+1] = f2tf(av.y);
            As[r][c+2] = f2tf(av.z); As[r][c+3] = f2tf(av.w);
            float4 bv = *reinterpret_cast<const float4*>(
                Wih + (size_t)(n0 + r) * I_DIM + kc + c);
            Bs[r][c]   = f2tf(bv.x); Bs[r][c+1] = f2tf(bv.y);
            Bs[r][c+2] = f2tf(bv.z); Bs[r][c+3] = f2tf(bv.w);
        }
        __syncthreads();
#pragma unroll
        for (int ks = 0; ks < 32; ks += 8) {
            uint32_t a[2][4];
#pragma unroll
            for (int mt = 0; mt < 2; mt++) {
                int m0 = mw * 32 + mt * 16;
                a[mt][0] = As[m0 + gid][ks + tq];
                a[mt][1] = As[m0 + gid + 8][ks + tq];
                a[mt][2] = As[m0 + gid][ks + tq + 4];
                a[mt][3] = As[m0 + gid + 8][ks + tq + 4];
            }
#pragma unroll
            for (int nt = 0; nt < 8; nt++) {
                int nn = nw * 64 + nt * 8;
                uint32_t b0 = Bs[nn + gid][ks + tq];
                uint32_t b1 = Bs[nn + gid][ks + tq + 4];
                mma8(acc[0][nt][0], acc[0][nt][1], acc[0][nt][2], acc[0][nt][3],
                     a[0][0], a[0][1], a[0][2], a[0][3], b0, b1);
                mma8(acc[1][nt][0], acc[1][nt][1], acc[1][nt][2], acc[1][nt][3],
                     a[1][0], a[1][1], a[1][2], a[1][3], b0, b1);
            }
        }
    }

#pragma unroll
    for (int mt = 0; mt < 2; mt++) {
        int row = mw * 32 + mt * 16 + gid;
#pragma unroll
        for (int nt = 0; nt < 8; nt++) {
            int col = n0 + nw * 64 + nt * 8 + tq * 2;
            float bs0 = bih[col]     + bhh[col];
            float bs1 = bih[col + 1] + bhh[col + 1];
            size_t r0 = ((size_t)s * 128 + row) * G4H + col;
            size_t r1 = ((size_t)s * 128 + row + 8) * G4H + col;
            g_xp[r0]     = acc[mt][nt][0] + bs0;
            g_xp[r0 + 1] = acc[mt][nt][1] + bs1;
            g_xp[r1]     = acc[mt][nt][2] + bs0;
            g_xp[r1 + 1] = acc[mt][nt][3] + bs1;
        }
    }
}

// ============================================================================
// Phase 2: persistent recurrence. CTA (p,q): batch rows [p*32,p*32+32),
// h-cols [q*16,q*16+16) -> gate cols {t*512 + q*16 + j}. W slice resident in
// smem (tf32). One global ticket barrier per step, ping-pong h buffers.
// ============================================================================
__global__ __launch_bounds__(256, 1) void lstm_kernel(const float* __restrict__ Whh) {
    extern __shared__ uint32_t sm[];
    uint32_t* Ws = sm;                               // [64][516]
    uint32_t* hs = sm + 64 * WS_PITCH;               // [32][516]
    float*    gs = (float*)(sm + (64 + 32) * WS_PITCH);  // [32][68]

    const int tid  = threadIdx.x;
    const int warp = tid >> 5, lane = tid & 31;
    const int gid  = lane >> 2, tq = lane & 3;
    const int mh = warp >> 2;        // 0,1 -> rows mh*16..+16
    const int nq = warp & 3;         // gate type 0..3 -> n cols nq*16..+16
    const int q = blockIdx.x & (QPARTS - 1);
    const int p = blockIdx.x >> 5;

    // Load resident W_hh slice (tf32 in smem). Row r (0..63): type r/16, k-col q*16 + r%16.
#pragma unroll
    for (int it = 0; it < 32; it++) {
        int id = tid + 256 * it;           // 8192 float4
        int r  = id >> 7;                  // 0..63
        int c4 = (id & 127) * 4;
        int grow = (r >> 4) * H_DIM + q * KP + (r & 15);
        float4 v = *reinterpret_cast<const float4*>(Whh + (size_t)grow * H_DIM + c4);
        uint32_t* d = Ws + r * WS_PITCH + c4;
        d[0] = f2tf(v.x); d[1] = f2tf(v.y); d[2] = f2tf(v.z); d[3] = f2tf(v.w);
    }

    // Persistent c-state: thread owns (b,k) pairs tid and tid+256.
    float creg[2] = {0.f, 0.f};
    const int kk = tid & 15;

    for (int t = 0; t < S_DIM; t++) {
        const float* xps = g_xp + ((size_t)t * B_DIM + p * BP) * G4H;

        // Prefetch this step's x_proj gate values (DRAM) early to overlap with MMA.
        float xv[2][4];
#pragma unroll
        for (int r2 = 0; r2 < 2; r2++) {
            int bl = (tid + r2 * 256) >> 4;
#pragma unroll
            for (int g = 0; g < 4; g++)
                xv[r2][g] = xps[(size_t)bl * G4H + g * 512 + q * KP + kk];
        }

        if (t > 0) {  // stage h_{t-1} (full H for our batch rows) into smem as tf32
            const float* hp = g_h[(t + 1) & 1] + (size_t)p * BP * H_DIM;
#pragma unroll
            for (int j = 0; j < 16; j++) {
                int id = tid + 256 * j;       // 4096 float4
                int r  = id >> 7;             // 0..31
                int c4 = (id & 127) * 4;
                float4 v = *reinterpret_cast<const float4*>(hp + (size_t)r * H_DIM + c4);
                uint32_t* d = hs + r * WS_PITCH + c4;
                d[0] = f2tf(v.x); d[1] = f2tf(v.y); d[2] = f2tf(v.z); d[3] = f2tf(v.w);
            }
        }
        __syncthreads();

        float acc[2][4] = {{0, 0, 0, 0}, {0, 0, 0, 0}};
        if (t > 0) {
            const int m0 = mh * 16;
#pragma unroll 4
            for (int ks = 0; ks < 64; ks++) {
                int k0 = ks * 8;
                uint32_t a0 = hs[(m0 + gid) * WS_PITCH + k0 + tq];
                uint32_t a1 = hs[(m0 + gid + 8) * WS_PITCH + k0 + tq];
                uint32_t a2 = hs[(m0 + gid) * WS_PITCH + k0 + tq + 4];
                uint32_t a3 = hs[(m0 + gid + 8) * WS_PITCH + k0 + tq + 4];
#pragma unroll
                for (int nt = 0; nt < 2; nt++) {
                    int nn = nq * 16 + nt * 8;
                    uint32_t b0 = Ws[(nn + gid) * WS_PITCH + k0 + tq];
                    uint32_t b1 = Ws[(nn + gid) * WS_PITCH + k0 + tq + 4];
                    mma8(acc[nt][0], acc[nt][1], acc[nt][2], acc[nt][3],
                         a0, a1, a2, a3, b0, b1);
                }
            }
        }

        // Scatter gate fragments to smem for the elementwise stage.
        {
            int row = mh * 16 + gid;
#pragma unroll
            for (int nt = 0; nt < 2; nt++) {
                int col = nq * 16 + nt * 8 + tq * 2;
                gs[row * GS_PITCH + col]           = acc[nt][0];
                gs[row * GS_PITCH + col + 1]       = acc[nt][1];
                gs[(row + 8) * GS_PITCH + col]     = acc[nt][2];
                gs[(row + 8) * GS_PITCH + col + 1] = acc[nt][3];
            }
        }
        __syncthreads();

        // Elementwise gate math + c update + h write (2 (b,k) pairs per thread).
        float* hdst = g_h[t & 1];
#pragma unroll
        for (int r2 = 0; r2 < 2; r2++) {
            int bl = (tid + r2 * 256) >> 4;
            float yi = gs[bl * GS_PITCH + kk]      + xv[r2][0];
            float yf = gs[bl * GS_PITCH + 16 + kk] + xv[r2][1];
            float yg = gs[bl * GS_PITCH + 32 + kk] + xv[r2][2];
            float yo = gs[bl * GS_PITCH + 48 + kk] + xv[r2][3];
            float ig = 1.f / (1.f + expf(-yi));
            float fg = 1.f / (1.f + expf(-yf));
            float gg = fmaxf(yg, 0.f);
            float og = 1.f / (1.f + expf(-yo));
            creg[r2] = fg * creg[r2] + ig * gg;
            hdst[(size_t)(p * BP + bl) * H_DIM + q * KP + kk] = og * creg[r2];
        }
        __syncthreads();

        // Global ticket barrier: monotonic counter, no reset, replay-safe.
        if (tid == 0) {
            __threadfence();
            unsigned long long ticket = atomicAdd(&g_bar, 1ULL);
            unsigned long long target = (ticket / NCTA + 1) * (unsigned long long)NCTA;
            while (*(volatile unsigned long long*)&g_bar < target) { }
            __threadfence();
        }
        __syncthreads();
    }
}

// ============================================================================
// Phase 3: out[b][o] = h_final[b] . fc_w[o] + fc_b[o]; h_final is g_h[1023&1]=g_h[1].
// ============================================================================
__global__ __launch_bounds__(320) void fc_kernel(const float* __restrict__ fcw,
                                                 const float* __restrict__ fcb,
                                                 float* __restrict__ out) {
    int b = blockIdx.x;
    int w = threadIdx.x >> 5, lane = threadIdx.x & 31;
    const float* h = g_h[1] + (size_t)b * H_DIM;
    float s = 0.f;
    for (int k = lane; k < H_DIM; k += 32) s += h[k] * fcw[w * H_DIM + k];
#pragma unroll
    for (int off = 16; off; off >>= 1) s += __shfl_down_sync(0xffffffffu, s, off);
    if (lane == 0) out[b * O_DIM + w] = s + fcb[w];
}

extern "C" void kernel_launch(void* const* d_in, const int* in_sizes, int n_in,
                              void* d_out, int out_size) {
    const float* x   = (const float*)d_in[0];
    const float* Wih = (const float*)d_in[1];
    const float* Whh = (const float*)d_in[2];
    const float* bih = (const float*)d_in[3];
    const float* bhh = (const float*)d_in[4];
    const float* fcw = (const float*)d_in[5];
    const float* fcb = (const float*)d_in[6];
    float* out = (float*)d_out;

    cudaFuncSetAttribute(lstm_kernel, cudaFuncAttributeMaxDynamicSharedMemorySize,
                         SMEM_LSTM_BYTES);

    xproj_kernel<<<dim3(16, 1024), 256>>>(x, Wih, bih, bhh);
    lstm_kernel<<<NCTA, 256, SMEM_LSTM_BYTES>>>(Whh);
    fc_kernel<<<B_DIM, 320>>>(fcw, fcb, out);
}